// round 11
// baseline (speedup 1.0000x reference)
#include <cuda_runtime.h>
#include <cuda_fp16.h>
#include <cstdint>

// ---------------------------------------------------------------------------
// Problem constants
// ---------------------------------------------------------------------------
#define BB 512      // batch
#define SS 256      // set size
#define DD 64       // feature dim (K)
#define HH 64       // n_hidden_sets
#define EE 8        // n_elements
#define HE 512      // H*E (N of GEMM)
#define BN_EPS 1e-5f

#define NCTA 304          // 2 per SM on GB300 (152 SMs)
#define K1_THREADS 256

// smem layout (bytes)
#define S_RING  0          // 3 x 16384 fp32 quarter staging (cp.async targets)
#define S_BUFA  49152      // fp16 X quarter buf 0 (8 KB)
#define S_BUFB  57344      // fp16 X quarter buf 1 (8 KB)
#define S_WFC   65536      // fc1_w transposed [h][j] (8 KB)
#define S_FB    73728      // fc1_b [32]
#define S_TSM   73856      // 2 x 64 floats (b-parity double buffer)
#define S_CTL   74368      // 8 ints: [0..3] ticket ring, [4] last flag
#define SM_TOTAL 74400

// ---------------------------------------------------------------------------
// Device scratch (no dynamic allocation allowed)
// ---------------------------------------------------------------------------
__device__ float g_u[BB * 32];      // fc1 output
__device__ int   g_ticket = 0;      // persistent work queue
__device__ int   g_done   = 0;      // CTA completion counter

__device__ __forceinline__ uint32_t smem_u32(const void* p) {
    uint32_t a;
    asm("{ .reg .u64 t; cvta.to.shared.u64 t, %1; cvt.u32.u64 %0, t; }" : "=r"(a) : "l"(p));
    return a;
}
__device__ __forceinline__ uint32_t swz(uint32_t off) {   // SW128: conflict-free ldmatrix
    return off ^ ((off >> 3) & 0x70);
}
__device__ __forceinline__ float lrelu(float x) { return fmaxf(x, 0.01f * x); }

__device__ __forceinline__ void ldsm_x4(uint32_t addr, uint32_t& r0, uint32_t& r1,
                                        uint32_t& r2, uint32_t& r3) {
    asm volatile("ldmatrix.sync.aligned.m8n8.x4.shared.b16 {%0,%1,%2,%3}, [%4];"
                 : "=r"(r0), "=r"(r1), "=r"(r2), "=r"(r3) : "r"(addr));
}
__device__ __forceinline__ void mma_fp16(float& c0, float& c1, float& c2, float& c3,
                                         uint32_t a0, uint32_t a1, uint32_t a2, uint32_t a3,
                                         uint32_t b0, uint32_t b1) {
    asm volatile("mma.sync.aligned.m16n8k16.row.col.f32.f16.f16.f32 "
                 "{%0,%1,%2,%3}, {%4,%5,%6,%7}, {%8,%9}, {%0,%1,%2,%3};"
                 : "+f"(c0), "+f"(c1), "+f"(c2), "+f"(c3)
                 : "r"(a0), "r"(a1), "r"(a2), "r"(a3), "r"(b0), "r"(b1));
}
#define CP_ASYNC16(saddr, gptr) \
    asm volatile("cp.async.ca.shared.global [%0], [%1], 16;" \
                 :: "r"(saddr), "l"(gptr) : "memory")
#define CP_COMMIT()  asm volatile("cp.async.commit_group;" ::: "memory")
#define CP_WAIT1()   asm volatile("cp.async.wait_group 1;" ::: "memory")

__device__ __forceinline__ uint32_t pack_h2(float lo, float hi) {
    __half2 h = __floats2half2_rn(lo, hi);
    return *(uint32_t*)&h;
}

// issue cp.async for one 16KB fp32 quarter (b, q) into ring slot
__device__ __forceinline__ void issue_quarter(uint32_t ring_s, const float* __restrict__ X,
                                              int b, int q, int tid) {
    const float* g = X + (size_t)b * (SS * DD) + q * 4096;
    #pragma unroll
    for (int j = 0; j < 4; j++) {
        int i = tid + j * 256;
        CP_ASYNC16(ring_s + i * 16, g + i * 4);
    }
}

// convert one fp32 ring quarter -> swizzled fp16 buffer
__device__ __forceinline__ void convert_quarter(char* smem, int ringoff, int bufoff, int tid) {
    #pragma unroll
    for (int j = 0; j < 4; j++) {
        int cc = tid + j * 256;            // float4 idx within quarter
        float4 v = *(const float4*)(smem + ringoff + cc * 16);
        int row = cc >> 4, k4 = (cc & 15) << 2;
        uint32_t sw = swz((uint32_t)row * 128u + (uint32_t)k4 * 2u);
        *(uint2*)(smem + bufoff + sw) = make_uint2(pack_h2(v.x, v.y), pack_h2(v.z, v.w));
    }
}

// ---------------------------------------------------------------------------
// Single persistent kernel: per-b tickets, cp.async 3-deep quarter pipeline
// ---------------------------------------------------------------------------
__global__ __launch_bounds__(K1_THREADS, 2)
void fused_all(const float* __restrict__ X, const float* __restrict__ Wc,
               const float* __restrict__ fc1_w, const float* __restrict__ fc1_b,
               const float* __restrict__ gamma, const float* __restrict__ beta,
               const float* __restrict__ fc2_w, const float* __restrict__ fc2_b,
               float* __restrict__ out) {
    extern __shared__ char smem[];
    const uint32_t sb = smem_u32(smem);
    const int tid  = threadIdx.x;
    const int hb   = tid >> 5;        // warp id == h-block
    const int lane = tid & 31;
    int* ctl = (int*)(smem + S_CTL);

    // ===== Phase A =====
    // stage fc1 weights (transposed) + bias
    for (int i = tid; i < 32 * HH; i += K1_THREADS) {
        int j = i >> 6, h = i & 63;
        ((float*)(smem + S_WFC))[h * 32 + j] = fc1_w[i];
    }
    if (tid < 32) ((float*)(smem + S_FB))[tid] = fc1_b[tid];

    // build B fragments directly from Wc (PTX m16n8k16 .col B mapping):
    // bf[e][2*ks]  : k = ks*16 + (lane%4)*2 + {0,1},  n = e*64 + hb*8 + lane/4
    // bf[e][2*ks+1]: k + 8
    uint32_t bf[EE][8];
    {
        const int n = hb * 8 + (lane >> 2);
        const int kb = (lane & 3) * 2;
        #pragma unroll
        for (int e = 0; e < EE; e++) {
            const float* wc_n = Wc + e * 64 + n;
            #pragma unroll
            for (int ks = 0; ks < 4; ks++) {
                int k0 = ks * 16 + kb;
                float w0 = __ldg(wc_n + (size_t)k0 * HE);
                float w1 = __ldg(wc_n + (size_t)(k0 + 1) * HE);
                bf[e][2 * ks] = pack_h2(w0, w1);
                w0 = __ldg(wc_n + (size_t)(k0 + 8) * HE);
                w1 = __ldg(wc_n + (size_t)(k0 + 9) * HE);
                bf[e][2 * ks + 1] = pack_h2(w0, w1);
            }
        }
    }

    // first two tickets
    if (tid == 0) {
        ctl[0] = atomicAdd(&g_ticket, 1);
        ctl[1] = atomicAdd(&g_ticket, 1);
    }
    __syncthreads();

    int b  = ctl[0];
    int ti = 1;                 // last-filled ticket slot
    int bi = 0;                 // b sequence parity

    // ===== prime the quarter pipeline =====
    if (b < BB) {
        issue_quarter(sb + S_RING + 0 * 16384, X, b, 0, tid); CP_COMMIT();
        issue_quarter(sb + S_RING + 1 * 16384, X, b, 1, tid); CP_COMMIT();
        CP_WAIT1();                              // quarter 0 arrived
        convert_quarter(smem, S_RING + 0 * 16384, S_BUFA, tid);
    }
    __syncthreads();

    int qg = 0;   // global quarter counter
    while (b < BB) {
        const int nb = ctl[ti & 3];              // next b (fetched >=1 b ago)
        float sacc0 = 0.0f, sacc1 = 0.0f;

        #pragma unroll
        for (int q = 0; q < 4; q++) {
            // fetch ticket for the b after nb (consumed next while-iteration)
            if (q == 0 && tid == 0 && nb < BB)
                ctl[(ti + 1) & 3] = atomicAdd(&g_ticket, 1);

            // prefetch quarter qg+2 -> ring[(qg+2)%3]
            {
                int pb = (q < 2) ? b : nb;
                int pq = (q + 2) & 3;
                if (pb < BB)
                    issue_quarter(sb + S_RING + ((qg + 2) % 3) * 16384, X, pb, pq, tid);
                CP_COMMIT();                      // commit (possibly empty) group
            }
            CP_WAIT1();                           // quarter qg+1 ready in ring

            // convert quarter qg+1 -> buf[(qg+1)&1]
            {
                int cb = (q < 3) ? b : nb;
                if (cb < BB)
                    convert_quarter(smem, S_RING + ((qg + 1) % 3) * 16384,
                                    ((qg + 1) & 1) ? S_BUFB : S_BUFA, tid);
            }

            // MMA over quarter qg from buf[qg&1] (4 m-tiles of 16 rows)
            const int bufoff = (qg & 1) ? S_BUFB : S_BUFA;
            #pragma unroll
            for (int mt = 0; mt < 4; mt++) {
                const int m0 = mt * 16;
                float c[EE][4];
                #pragma unroll
                for (int e = 0; e < EE; e++)
                    #pragma unroll
                    for (int i = 0; i < 4; i++) c[e][i] = 0.0f;

                #pragma unroll
                for (int ks = 0; ks < 4; ks++) {
                    uint32_t off = (uint32_t)(m0 + (lane & 15)) * 128u
                                 + (uint32_t)ks * 32u + (uint32_t)(lane >> 4) * 16u;
                    uint32_t sw = swz(off);
                    uint32_t a0, a1, a2, a3;
                    ldsm_x4(sb + bufoff + sw, a0, a1, a2, a3);
                    #pragma unroll
                    for (int e = 0; e < EE; e++)
                        mma_fp16(c[e][0], c[e][1], c[e][2], c[e][3],
                                 a0, a1, a2, a3, bf[e][2 * ks], bf[e][2 * ks + 1]);
                }

                // max over E first (lrelu monotone -> commutes exactly)
                float v0 = c[0][0], v1 = c[0][1], v2 = c[0][2], v3 = c[0][3];
                #pragma unroll
                for (int e = 1; e < EE; e++) {
                    v0 = fmaxf(v0, c[e][0]);
                    v1 = fmaxf(v1, c[e][1]);
                    v2 = fmaxf(v2, c[e][2]);
                    v3 = fmaxf(v3, c[e][3]);
                }
                sacc0 += lrelu(v0) + lrelu(v2);   // col h = hb*8 + (lane%4)*2
                sacc1 += lrelu(v1) + lrelu(v3);   // col h+1
            }

            if (q == 3) {      // flush pooled sums into parity tsm before barrier
                #pragma unroll
                for (int o = 4; o <= 16; o <<= 1) {
                    sacc0 += __shfl_xor_sync(0xffffffffu, sacc0, o);
                    sacc1 += __shfl_xor_sync(0xffffffffu, sacc1, o);
                }
                if (lane < 4) {
                    float* tsm = (float*)(smem + S_TSM) + (bi & 1) * HH;
                    tsm[hb * 8 + lane * 2]     = sacc0;
                    tsm[hb * 8 + lane * 2 + 1] = sacc1;
                }
            }
            __syncthreads();   // buf/ring/tsm rotation barrier (1 per quarter)
            qg++;
        }

        // fc1 for b (warp 0, overlapped with other warps starting next b)
        if (tid < 32) {
            const float* tsm = (const float*)(smem + S_TSM) + (bi & 1) * HH;
            const float* wfc = (const float*)(smem + S_WFC);
            float uacc = ((const float*)(smem + S_FB))[tid];
            #pragma unroll 8
            for (int h = 0; h < HH; h++)
                uacc = fmaf(tsm[h], wfc[h * 32 + tid], uacc);
            g_u[b * 32 + tid] = uacc;
        }

        b = nb; ti++; bi++;
    }

    // ===== Phase C: last CTA runs BatchNorm + LeakyReLU + fc2 inline =====
    __threadfence();
    if (tid == 0) {
        int old = atomicAdd(&g_done, 1);
        ctl[4] = (old == NCTA - 1) ? 1 : 0;
    }
    __syncthreads();
    if (!ctl[4]) return;

    // stage g_u into padded smem US[b][j] stride 33 (ring is dead here)
    float* US = (float*)(smem + S_RING);
    for (int i = tid; i < BB * 32; i += K1_THREADS)
        US[(i >> 5) * 33 + (i & 31)] = g_u[i];
    float* PS   = US + BB * 33;                  // [8][32] partials (67584B ok)
    float* MEAN = PS + 256;                      // [32]
    float* RS   = MEAN + 32;                     // [32]
    __syncthreads();

    const int j = tid & 31, g = tid >> 5;        // 8 groups x 32 features
    {
        float s = 0.0f;
        #pragma unroll 8
        for (int bb = g * 64; bb < g * 64 + 64; bb++) s += US[bb * 33 + j];
        PS[g * 32 + j] = s;
    }
    __syncthreads();
    if (tid < 32) {
        float m = 0.0f;
        #pragma unroll
        for (int g2 = 0; g2 < 8; g2++) m += PS[g2 * 32 + tid];
        MEAN[tid] = m * (1.0f / (float)BB);
    }
    __syncthreads();
    {
        float mu = MEAN[j], s = 0.0f;
        #pragma unroll 8
        for (int bb = g * 64; bb < g * 64 + 64; bb++) {
            float d = US[bb * 33 + j] - mu;
            s += d * d;
        }
        PS[g * 32 + j] = s;
    }
    __syncthreads();
    if (tid < 32) {
        float v = 0.0f;
        #pragma unroll
        for (int g2 = 0; g2 < 8; g2++) v += PS[g2 * 32 + tid];
        RS[tid] = rsqrtf(v * (1.0f / (float)BB) + BN_EPS);
    }
    __syncthreads();

    for (int bb = tid; bb < BB; bb += K1_THREADS) {
        float a = __ldg(&fc2_b[0]);
        #pragma unroll
        for (int j2 = 0; j2 < 32; j2++) {
            float y = (US[bb * 33 + j2] - MEAN[j2]) * RS[j2] * __ldg(&gamma[j2]) + __ldg(&beta[j2]);
            a = fmaf(lrelu(y), __ldg(&fc2_w[j2]), a);
        }
        out[bb] = a;
    }

    // reset counters for next graph replay
    if (tid == 0) { g_ticket = 0; g_done = 0; }
}

// ---------------------------------------------------------------------------
extern "C" void kernel_launch(void* const* d_in, const int* in_sizes, int n_in,
                              void* d_out, int out_size) {
    const float* X     = (const float*)d_in[0];
    const float* Wc    = (const float*)d_in[1];
    const float* fc1_w = (const float*)d_in[2];
    const float* fc1_b = (const float*)d_in[3];
    const float* gamma = (const float*)d_in[4];
    const float* beta  = (const float*)d_in[5];
    const float* fc2_w = (const float*)d_in[6];
    const float* fc2_b = (const float*)d_in[7];
    float* out = (float*)d_out;

    cudaFuncSetAttribute(fused_all, cudaFuncAttributeMaxDynamicSharedMemorySize, SM_TOTAL);
    fused_all<<<NCTA, K1_THREADS, SM_TOTAL>>>(X, Wc, fc1_w, fc1_b,
                                              gamma, beta, fc2_w, fc2_b, out);
}